// round 7
// baseline (speedup 1.0000x reference)
#include <cuda_runtime.h>
#include <cstddef>

// Problem constants (fixed by the reference)
#define BB 8
#define DD 32
#define NPIX 262144          // 512*512
#define KK 16

// Pass-1 tiling: 32 pixel-chunks x 4 d-groups x 8 images = 1024 blocks
#define P1_CHUNK  8192
#define P1_NCHUNK (NPIX / P1_CHUNK)    // 32

// Pass-2 tiling: one float4 (4 pixels) per thread
#define P2_TPB    256
#define P2_BLOCKS (NPIX / 4 / P2_TPB)  // 256 blocks per image

// Scratch (no cudaMalloc allowed). Partials fully overwritten each launch.
__device__ float g_part[BB * P1_NCHUNK * KK * DD];   // per-chunk partial sums
__device__ float g_cntp[BB * P1_NCHUNK * KK];        // per-chunk partial counts
__device__ float g_counts[BB * KK];
__device__ float g_means[BB * KK * DD];

// ---------------------------------------------------------------------------
// Pass 1: per-image, per-chunk partial segment sums.
// Block = 256 threads = 8 warps; warp w owns plane d = dg*8 + w over the
// whole 8192-px chunk. Two independent LDG.128 per lane per iteration.
// Per-lane privatized smem bins (stride 32): LDS/FADD/STS conflict-free.
// 26 KB smem / 256 thr -> 8 blocks/SM -> 64 warps (100% occupancy).
// ---------------------------------------------------------------------------
__global__ __launch_bounds__(256) void k_pass1(const float* __restrict__ emb,
                                               const int* __restrict__ gt,
                                               float* out) {
    __shared__ float acc[8 * KK * 32];           // [w][k][lane]  16 KB
    __shared__ float cnt[KK * 32];               // [k][lane]      2 KB
    __shared__ uchar4 lab4[P1_CHUNK / 4];        //                8 KB

    const int b  = blockIdx.z;
    const int dg = blockIdx.y;                   // d group: 0..3
    const int c  = blockIdx.x;                   // chunk
    const int p0 = c * P1_CHUNK;
    const int tid = threadIdx.x;
    const int w   = tid >> 5;
    const int lane = tid & 31;
    const int d = dg * 8 + w;

    if (b == 0 && dg == 0 && c == 0 && tid == 0) out[0] = 0.0f;

    for (int j = tid; j < 8 * KK * 32; j += 256) acc[j] = 0.0f;
    for (int j = tid; j < KK * 32; j += 256) cnt[j] = 0.0f;

    // Stage labels once (int4 -> uchar4): 2048 entries
    const int4* g4 = (const int4*)(gt + (size_t)b * NPIX + p0);
    for (int j = tid; j < P1_CHUNK / 4; j += 256) {
        int4 t = g4[j];
        lab4[j] = make_uchar4((unsigned char)t.x, (unsigned char)t.y,
                              (unsigned char)t.z, (unsigned char)t.w);
    }
    __syncthreads();

    const float4* e4 = (const float4*)(emb + ((size_t)(b * DD + d)) * NPIX + p0);
    const bool docnt = (dg == 0) && (w == 0);

    float* aw = acc + (w * KK) * 32 + lane;
    float* cw = cnt + lane;

    // 2048 float4s per plane-chunk per warp; 64 per lane, two per iteration.
    #pragma unroll 4
    for (int i = 0; i < 32; i++) {
        int idx = i * 64 + lane;
        float4 va = __ldcs(&e4[idx]);
        float4 vb = __ldcs(&e4[idx + 32]);
        uchar4 ka = lab4[idx];
        uchar4 kb = lab4[idx + 32];
        aw[(int)ka.x * 32] += va.x;
        aw[(int)ka.y * 32] += va.y;
        aw[(int)ka.z * 32] += va.z;
        aw[(int)ka.w * 32] += va.w;
        aw[(int)kb.x * 32] += vb.x;
        aw[(int)kb.y * 32] += vb.y;
        aw[(int)kb.z * 32] += vb.z;
        aw[(int)kb.w * 32] += vb.w;
        if (docnt) {
            cw[(int)ka.x * 32] += 1.0f;
            cw[(int)ka.y * 32] += 1.0f;
            cw[(int)ka.z * 32] += 1.0f;
            cw[(int)ka.w * 32] += 1.0f;
            cw[(int)kb.x * 32] += 1.0f;
            cw[(int)kb.y * 32] += 1.0f;
            cw[(int)kb.z * 32] += 1.0f;
            cw[(int)kb.w * 32] += 1.0f;
        }
    }
    __syncwarp();

    // Epilogue: rows acc[w][k][0..31] are contiguous 128B. 2 lanes per k-row,
    // each reads 4 float4, sum, 1 shuffle, STG (no atomics).
    {
        const int k = lane >> 1;
        const int h = lane & 1;
        const float4* row = (const float4*)(acc + ((w * KK + k) << 5) + (h << 4));
        float4 r0 = row[0], r1 = row[1], r2 = row[2], r3 = row[3];
        float s = ((r0.x + r0.y) + (r0.z + r0.w)) + ((r1.x + r1.y) + (r1.z + r1.w))
                + ((r2.x + r2.y) + (r2.z + r2.w)) + ((r3.x + r3.y) + (r3.z + r3.w));
        s += __shfl_down_sync(0xffffffffu, s, 1);
        if (h == 0)
            g_part[(((b * P1_NCHUNK + c) * KK + k) * DD) + d] = s;
    }
    if (docnt) {
        const int k = lane >> 1;
        const int h = lane & 1;
        const float4* row = (const float4*)(cnt + (k << 5) + (h << 4));
        float4 r0 = row[0], r1 = row[1], r2 = row[2], r3 = row[3];
        float s = ((r0.x + r0.y) + (r0.z + r0.w)) + ((r1.x + r1.y) + (r1.z + r1.w))
                + ((r2.x + r2.y) + (r2.z + r2.w)) + ((r3.x + r3.y) + (r3.z + r3.w));
        s += __shfl_down_sync(0xffffffffu, s, 1);
        if (h == 0)
            g_cntp[(b * P1_NCHUNK + c) * KK + k] = s;
    }
}

// ---------------------------------------------------------------------------
// Finalize: reduce partials -> counts & means; pairwise push loss; reg loss.
// One block per image.
// ---------------------------------------------------------------------------
__global__ __launch_bounds__(256) void k_finalize(float* out) {
    __shared__ float m[KK * 33];    // padded means
    __shared__ float cs[KK];
    __shared__ float red[256];

    const int b = blockIdx.x;
    const int tid = threadIdx.x;

    if (tid < KK) {
        float s = 0.0f;
        #pragma unroll 4
        for (int c = 0; c < P1_NCHUNK; c++)
            s += g_cntp[(b * P1_NCHUNK + c) * KK + tid];
        float cv = fmaxf(s, 1.0f);
        cs[tid] = cv;
        g_counts[b * KK + tid] = cv;
    }
    __syncthreads();

    for (int j = tid; j < KK * DD; j += 256) {
        int k = j >> 5, d = j & 31;
        float s = 0.0f;
        #pragma unroll 4
        for (int c = 0; c < P1_NCHUNK; c++)
            s += g_part[(((b * P1_NCHUNK + c) * KK + k) * DD) + d];
        float mean = s / cs[k];
        g_means[(b * KK + k) * DD + d] = mean;
        m[k * 33 + d] = mean;
    }
    __syncthreads();

    // Pairwise hinge on cluster-mean distances: thread -> (i,j), upper tri only.
    const int i = tid >> 4;
    const int j = tid & 15;
    float contrib = 0.0f;
    if (j > i) {
        float d2 = 0.0f;
        #pragma unroll
        for (int d = 0; d < DD; d++) {
            float df = m[i * 33 + d] - m[j * 33 + d];
            d2 = fmaf(df, df, d2);
        }
        float pd = sqrtf(d2);             // i<j: diagonal eye irrelevant
        float h = fmaxf(3.0f - pd, 0.0f); // 2 * DIST_THETA = 3.0
        contrib = h * h;
    }

    float reg = 0.0f;
    if (tid < KK) {
        float n2 = 0.0f;
        #pragma unroll
        for (int d = 0; d < DD; d++) {
            float v = m[tid * 33 + d];
            n2 = fmaf(v, v, n2);
        }
        reg = sqrtf(n2);
    }

    red[tid] = contrib * (1.0f / (KK * (KK - 1))) + 0.001f * reg * (1.0f / KK);
    __syncthreads();
    for (int off = 128; off; off >>= 1) {
        if (tid < off) red[tid] += red[tid + off];
        __syncthreads();
    }
    if (tid == 0) atomicAdd(out, red[0] * (1.0f / BB));
}

// ---------------------------------------------------------------------------
// Pass 2: per-pixel hinge variance loss, folded directly into the scalar.
// One float4 (4 consecutive pixels) per thread; batched LDG.128s.
// ---------------------------------------------------------------------------
__global__ __launch_bounds__(P2_TPB) void k_pass2(const float* __restrict__ emb,
                                                  const int* __restrict__ gt,
                                                  float* out) {
    __shared__ float m[KK * 33];
    __shared__ float wk[KK];
    __shared__ float red[P2_TPB / 32];

    const int b  = blockIdx.y;
    const int tid = threadIdx.x;
    const int lane = tid & 31;
    const int w = tid >> 5;
    const int p4 = blockIdx.x * P2_TPB + tid;    // float4 index

    for (int j = tid; j < KK * DD; j += P2_TPB)
        m[(j / DD) * 33 + (j % DD)] = g_means[b * KK * DD + j];
    if (tid < KK)
        wk[tid] = 1.0f / ((float)KK * fmaxf(g_counts[b * KK + tid], 1.0f));
    __syncthreads();

    const float4* e4 = (const float4*)(emb + (size_t)b * DD * NPIX);
    const int4 kk = ((const int4*)(gt + (size_t)b * NPIX))[p4];

    const float* m0 = m + kk.x * 33;
    const float* m1 = m + kk.y * 33;
    const float* m2 = m + kk.z * 33;
    const float* m3 = m + kk.w * 33;

    float a0 = 0.0f, a1 = 0.0f, a2 = 0.0f, a3 = 0.0f;
    #pragma unroll
    for (int g = 0; g < 4; g++) {
        float4 v[8];
        #pragma unroll
        for (int j = 0; j < 8; j++)
            v[j] = __ldcs(&e4[(size_t)(g * 8 + j) * (NPIX / 4) + p4]);
        #pragma unroll
        for (int j = 0; j < 8; j++) {
            const int d = g * 8 + j;
            float t;
            t = v[j].x - m0[d]; a0 = fmaf(t, t, a0);
            t = v[j].y - m1[d]; a1 = fmaf(t, t, a1);
            t = v[j].z - m2[d]; a2 = fmaf(t, t, a2);
            t = v[j].w - m3[d]; a3 = fmaf(t, t, a3);
        }
    }

    float h, lacc = 0.0f;
    h = fmaxf(sqrtf(a0) - 0.5f, 0.0f); lacc = fmaf(h * h, wk[kk.x], lacc);
    h = fmaxf(sqrtf(a1) - 0.5f, 0.0f); lacc = fmaf(h * h, wk[kk.y], lacc);
    h = fmaxf(sqrtf(a2) - 0.5f, 0.0f); lacc = fmaf(h * h, wk[kk.z], lacc);
    h = fmaxf(sqrtf(a3) - 0.5f, 0.0f); lacc = fmaf(h * h, wk[kk.w], lacc);

    #pragma unroll
    for (int off = 16; off; off >>= 1)
        lacc += __shfl_down_sync(0xffffffffu, lacc, off);
    if (lane == 0) red[w] = lacc;
    __syncthreads();
    if (tid == 0) {
        float s = 0.0f;
        #pragma unroll
        for (int i = 0; i < P2_TPB / 32; i++) s += red[i];
        atomicAdd(out, s * (1.0f / BB));
    }
}

// ---------------------------------------------------------------------------
extern "C" void kernel_launch(void* const* d_in, const int* in_sizes, int n_in,
                              void* d_out, int out_size) {
    int ei = 0, gi = 1;
    // Defensive: identify inputs by size (embeddings = 67108864, gt = 2097152)
    if (n_in >= 2 && in_sizes[0] == BB * NPIX) { ei = 1; gi = 0; }

    const float* emb = (const float*)d_in[ei];
    const int*   gt  = (const int*)d_in[gi];
    float* out = (float*)d_out;

    k_pass1<<<dim3(P1_NCHUNK, 4, BB), 256>>>(emb, gt, out);
    k_finalize<<<BB, 256>>>(out);
    k_pass2<<<dim3(P2_BLOCKS, BB), P2_TPB>>>(emb, gt, out);
}

// round 8
// speedup vs baseline: 1.3067x; 1.3067x over previous
#include <cuda_runtime.h>
#include <cstddef>

// Problem constants (fixed by the reference)
#define BB 8
#define DD 32
#define NPIX 262144          // 512*512
#define KK 16

// Pass-1 tiling: 32 pixel-chunks x 2 d-groups x 8 images = 512 blocks
#define P1_CHUNK  8192
#define P1_NCHUNK (NPIX / P1_CHUNK)    // 32

// Pass-2 tiling: one float4 (4 pixels) per thread
#define P2_TPB    256
#define P2_BLOCKS (NPIX / 4 / P2_TPB)  // 256 blocks per image

// Scratch (no cudaMalloc allowed). Partials fully overwritten each launch.
__device__ float g_part[BB * P1_NCHUNK * KK * DD];   // per-chunk partial sums
__device__ float g_cntp[BB * P1_NCHUNK * KK];        // per-chunk partial counts
__device__ float g_counts[BB * KK];
__device__ float g_means[BB * KK * DD];

// ---------------------------------------------------------------------------
// Pass 1: per-image, per-chunk partial segment sums.
// Block = 512 threads = 16 warps; warp w owns plane d = dg*16 + w over the
// whole 8192-px chunk. Software-pipelined: iteration i+1's loads (2x LDG.128
// + 2 label words) are issued BEFORE iteration i's smem RMW burst, carried in
// registers -> DRAM latency overlapped with RMW work instead of exposed.
// Per-lane privatized smem bins (stride 32): LDS/FADD/STS conflict-free.
// ---------------------------------------------------------------------------
__global__ __launch_bounds__(512) void k_pass1(const float* __restrict__ emb,
                                               const int* __restrict__ gt,
                                               float* out) {
    __shared__ float acc[16 * KK * 32];          // [w][k][lane]  32 KB
    __shared__ float cnt[KK * 32];               // [k][lane]      2 KB
    __shared__ unsigned int labw[P1_CHUNK / 4];  // packed 4x u8    8 KB

    const int b  = blockIdx.z;
    const int dg = blockIdx.y;                   // d group: 0 or 1
    const int c  = blockIdx.x;                   // chunk
    const int p0 = c * P1_CHUNK;
    const int tid = threadIdx.x;
    const int w   = tid >> 5;
    const int lane = tid & 31;
    const int d = dg * 16 + w;

    if (b == 0 && dg == 0 && c == 0 && tid == 0) out[0] = 0.0f;

    for (int j = tid; j < 16 * KK * 32; j += 512) acc[j] = 0.0f;
    if (tid < KK * 32) cnt[tid] = 0.0f;

    // Stage labels once (int4 -> packed u8x4): 2048 words
    const int4* g4 = (const int4*)(gt + (size_t)b * NPIX + p0);
    for (int j = tid; j < P1_CHUNK / 4; j += 512) {
        int4 t = g4[j];
        labw[j] = (unsigned)t.x | ((unsigned)t.y << 8) |
                  ((unsigned)t.z << 16) | ((unsigned)t.w << 24);
    }
    __syncthreads();

    const float4* e4 = (const float4*)(emb + ((size_t)(b * DD + d)) * NPIX + p0);
    const bool docnt = (dg == 0) && (w == 0);

    float* aw = acc + (w * KK) * 32 + lane;
    float* cw = cnt + lane;

    #define RMW(V, KW) do {                                             \
        unsigned kw_ = (KW);                                            \
        aw[(int)(kw_ & 15u) * 32]         += (V).x;                     \
        aw[(int)((kw_ >> 8) & 15u) * 32]  += (V).y;                     \
        aw[(int)((kw_ >> 16) & 15u) * 32] += (V).z;                     \
        aw[(int)(kw_ >> 24) * 32]         += (V).w;                     \
    } while (0)
    #define CNT(KW) do {                                                \
        unsigned kw_ = (KW);                                            \
        cw[(int)(kw_ & 15u) * 32]         += 1.0f;                      \
        cw[(int)((kw_ >> 8) & 15u) * 32]  += 1.0f;                      \
        cw[(int)((kw_ >> 16) & 15u) * 32] += 1.0f;                      \
        cw[(int)(kw_ >> 24) * 32]         += 1.0f;                      \
    } while (0)

    // 2048 float4s per plane-chunk per warp; 64 per lane, two per iteration.
    // Software pipeline, prefetch distance 1.
    float4 va = __ldcs(&e4[lane]);
    float4 vb = __ldcs(&e4[lane + 32]);
    unsigned ka = labw[lane];
    unsigned kb = labw[lane + 32];

    #pragma unroll 1
    for (int i = 0; i < 31; i++) {
        const int nidx = (i + 1) * 64 + lane;
        float4 na = __ldcs(&e4[nidx]);
        float4 nb = __ldcs(&e4[nidx + 32]);
        unsigned nka = labw[nidx];
        unsigned nkb = labw[nidx + 32];

        RMW(va, ka);
        RMW(vb, kb);
        if (docnt) { CNT(ka); CNT(kb); }

        va = na; vb = nb; ka = nka; kb = nkb;
    }
    RMW(va, ka);
    RMW(vb, kb);
    if (docnt) { CNT(ka); CNT(kb); }
    #undef RMW
    #undef CNT
    __syncwarp();

    // Epilogue: rows acc[w][k][0..31] are contiguous 128B. 2 lanes per k-row,
    // each reads 4 float4, sum, 1 shuffle, STG (no atomics).
    {
        const int k = lane >> 1;
        const int h = lane & 1;
        const float4* row = (const float4*)(acc + ((w * KK + k) << 5) + (h << 4));
        float4 r0 = row[0], r1 = row[1], r2 = row[2], r3 = row[3];
        float s = ((r0.x + r0.y) + (r0.z + r0.w)) + ((r1.x + r1.y) + (r1.z + r1.w))
                + ((r2.x + r2.y) + (r2.z + r2.w)) + ((r3.x + r3.y) + (r3.z + r3.w));
        s += __shfl_down_sync(0xffffffffu, s, 1);
        if (h == 0)
            g_part[(((b * P1_NCHUNK + c) * KK + k) * DD) + d] = s;
    }
    if (docnt) {
        const int k = lane >> 1;
        const int h = lane & 1;
        const float4* row = (const float4*)(cnt + (k << 5) + (h << 4));
        float4 r0 = row[0], r1 = row[1], r2 = row[2], r3 = row[3];
        float s = ((r0.x + r0.y) + (r0.z + r0.w)) + ((r1.x + r1.y) + (r1.z + r1.w))
                + ((r2.x + r2.y) + (r2.z + r2.w)) + ((r3.x + r3.y) + (r3.z + r3.w));
        s += __shfl_down_sync(0xffffffffu, s, 1);
        if (h == 0)
            g_cntp[(b * P1_NCHUNK + c) * KK + k] = s;
    }
}

// ---------------------------------------------------------------------------
// Finalize: reduce partials -> counts & means; pairwise push loss; reg loss.
// One block per image.
// ---------------------------------------------------------------------------
__global__ __launch_bounds__(256) void k_finalize(float* out) {
    __shared__ float m[KK * 33];    // padded means
    __shared__ float cs[KK];
    __shared__ float red[256];

    const int b = blockIdx.x;
    const int tid = threadIdx.x;

    if (tid < KK) {
        float s = 0.0f;
        #pragma unroll 4
        for (int c = 0; c < P1_NCHUNK; c++)
            s += g_cntp[(b * P1_NCHUNK + c) * KK + tid];
        float cv = fmaxf(s, 1.0f);
        cs[tid] = cv;
        g_counts[b * KK + tid] = cv;
    }
    __syncthreads();

    for (int j = tid; j < KK * DD; j += 256) {
        int k = j >> 5, d = j & 31;
        float s = 0.0f;
        #pragma unroll 4
        for (int c = 0; c < P1_NCHUNK; c++)
            s += g_part[(((b * P1_NCHUNK + c) * KK + k) * DD) + d];
        float mean = s / cs[k];
        g_means[(b * KK + k) * DD + d] = mean;
        m[k * 33 + d] = mean;
    }
    __syncthreads();

    // Pairwise hinge on cluster-mean distances: thread -> (i,j), upper tri only.
    const int i = tid >> 4;
    const int j = tid & 15;
    float contrib = 0.0f;
    if (j > i) {
        float d2 = 0.0f;
        #pragma unroll
        for (int d = 0; d < DD; d++) {
            float df = m[i * 33 + d] - m[j * 33 + d];
            d2 = fmaf(df, df, d2);
        }
        float pd = sqrtf(d2);             // i<j: diagonal eye irrelevant
        float h = fmaxf(3.0f - pd, 0.0f); // 2 * DIST_THETA = 3.0
        contrib = h * h;
    }

    float reg = 0.0f;
    if (tid < KK) {
        float n2 = 0.0f;
        #pragma unroll
        for (int d = 0; d < DD; d++) {
            float v = m[tid * 33 + d];
            n2 = fmaf(v, v, n2);
        }
        reg = sqrtf(n2);
    }

    red[tid] = contrib * (1.0f / (KK * (KK - 1))) + 0.001f * reg * (1.0f / KK);
    __syncthreads();
    for (int off = 128; off; off >>= 1) {
        if (tid < off) red[tid] += red[tid + off];
        __syncthreads();
    }
    if (tid == 0) atomicAdd(out, red[0] * (1.0f / BB));
}

// ---------------------------------------------------------------------------
// Pass 2: per-pixel hinge variance loss, folded directly into the scalar.
// One float4 (4 consecutive pixels) per thread; batched LDG.128s.
// ---------------------------------------------------------------------------
__global__ __launch_bounds__(P2_TPB) void k_pass2(const float* __restrict__ emb,
                                                  const int* __restrict__ gt,
                                                  float* out) {
    __shared__ float m[KK * 33];
    __shared__ float wk[KK];
    __shared__ float red[P2_TPB / 32];

    const int b  = blockIdx.y;
    const int tid = threadIdx.x;
    const int lane = tid & 31;
    const int w = tid >> 5;
    const int p4 = blockIdx.x * P2_TPB + tid;    // float4 index

    for (int j = tid; j < KK * DD; j += P2_TPB)
        m[(j / DD) * 33 + (j % DD)] = g_means[b * KK * DD + j];
    if (tid < KK)
        wk[tid] = 1.0f / ((float)KK * fmaxf(g_counts[b * KK + tid], 1.0f));
    __syncthreads();

    const float4* e4 = (const float4*)(emb + (size_t)b * DD * NPIX);
    const int4 kk = ((const int4*)(gt + (size_t)b * NPIX))[p4];

    const float* m0 = m + kk.x * 33;
    const float* m1 = m + kk.y * 33;
    const float* m2 = m + kk.z * 33;
    const float* m3 = m + kk.w * 33;

    float a0 = 0.0f, a1 = 0.0f, a2 = 0.0f, a3 = 0.0f;
    #pragma unroll
    for (int g = 0; g < 4; g++) {
        float4 v[8];
        #pragma unroll
        for (int j = 0; j < 8; j++)
            v[j] = __ldcs(&e4[(size_t)(g * 8 + j) * (NPIX / 4) + p4]);
        #pragma unroll
        for (int j = 0; j < 8; j++) {
            const int d = g * 8 + j;
            float t;
            t = v[j].x - m0[d]; a0 = fmaf(t, t, a0);
            t = v[j].y - m1[d]; a1 = fmaf(t, t, a1);
            t = v[j].z - m2[d]; a2 = fmaf(t, t, a2);
            t = v[j].w - m3[d]; a3 = fmaf(t, t, a3);
        }
    }

    float h, lacc = 0.0f;
    h = fmaxf(sqrtf(a0) - 0.5f, 0.0f); lacc = fmaf(h * h, wk[kk.x], lacc);
    h = fmaxf(sqrtf(a1) - 0.5f, 0.0f); lacc = fmaf(h * h, wk[kk.y], lacc);
    h = fmaxf(sqrtf(a2) - 0.5f, 0.0f); lacc = fmaf(h * h, wk[kk.z], lacc);
    h = fmaxf(sqrtf(a3) - 0.5f, 0.0f); lacc = fmaf(h * h, wk[kk.w], lacc);

    #pragma unroll
    for (int off = 16; off; off >>= 1)
        lacc += __shfl_down_sync(0xffffffffu, lacc, off);
    if (lane == 0) red[w] = lacc;
    __syncthreads();
    if (tid == 0) {
        float s = 0.0f;
        #pragma unroll
        for (int i = 0; i < P2_TPB / 32; i++) s += red[i];
        atomicAdd(out, s * (1.0f / BB));
    }
}

// ---------------------------------------------------------------------------
extern "C" void kernel_launch(void* const* d_in, const int* in_sizes, int n_in,
                              void* d_out, int out_size) {
    int ei = 0, gi = 1;
    // Defensive: identify inputs by size (embeddings = 67108864, gt = 2097152)
    if (n_in >= 2 && in_sizes[0] == BB * NPIX) { ei = 1; gi = 0; }

    const float* emb = (const float*)d_in[ei];
    const int*   gt  = (const int*)d_in[gi];
    float* out = (float*)d_out;

    k_pass1<<<dim3(P1_NCHUNK, 2, BB), 512>>>(emb, gt, out);
    k_finalize<<<BB, 256>>>(out);
    k_pass2<<<dim3(P2_BLOCKS, BB), P2_TPB>>>(emb, gt, out);
}